// round 6
// baseline (speedup 1.0000x reference)
#include <cuda_runtime.h>

#define BDIM   512
#define TILE_M 64
#define NCH    512
#define HID    64
#define XS     516   // x/tanh smem row stride (floats)
#define HS     68    // h1 smem row stride
#define WS2F4  65    // w2 stage row stride in float4 units (260 floats)

// Pre-transposed weights (written by prep_kernel each launch; deterministic).
__device__ __align__(16) float g_w1t[513 * 64];   // w1t[k][h] = W1[h][k], k=512 = epsilon column
__device__ __align__(16) float g_w2t[64 * 512];   // w2t[h][n] = W2[n][h]

__global__ void prep_kernel(const float* __restrict__ W1, const float* __restrict__ W2) {
    int idx = blockIdx.x * blockDim.x + threadIdx.x;
    if (idx < 513 * 64) {
        int k = idx >> 6, h = idx & 63;
        g_w1t[idx] = W1[h * 513 + k];
    }
    if (idx < 64 * 512) {
        int h = idx >> 9, n = idx & 511;
        g_w2t[idx] = W2[n * 64 + h];
    }
}

__device__ __forceinline__ float fast_tanh(float x) {
    float ax = fabsf(x);
    float e  = __expf(-2.0f * ax);
    float t  = __fdividef(1.0f - e, 1.0f + e);
    return copysignf(t, x);
}

__device__ __forceinline__ void fma4(float* acc, float a, float4 wv) {
    acc[0] = fmaf(a, wv.x, acc[0]);
    acc[1] = fmaf(a, wv.y, acc[1]);
    acc[2] = fmaf(a, wv.z, acc[2]);
    acc[3] = fmaf(a, wv.w, acc[3]);
}

// smem float counts
#define N_SX   (TILE_M * XS)      // 33024
#define N_SW   16640              // max(w1 stage 8192, w2 stage 64*260=16640)
#define N_SH1  (TILE_M * HS)      // 4352

__global__ __launch_bounds__(BDIM, 1)
void fused_kernel(const float* __restrict__ x_cpm,
                  const float* __restrict__ x_cons,
                  const float* __restrict__ cap,
                  const float* __restrict__ b1,
                  const float* __restrict__ b2,
                  float* __restrict__ out) {
    extern __shared__ float sm[];
    float* s_x     = sm;                    // x tile, later tanh buffer
    float* s_w     = s_x + N_SX;            // weight stage
    float* s_h1    = s_w + N_SW;
    float* s_cap   = s_h1 + N_SH1;          // 512
    float* s_icap  = s_cap + 512;           // 512
    float* s_eps   = s_icap + 512;          // 64
    float* s_scale = s_eps + 64;            // 64
    float* s_wred  = s_scale + 64;          // 128
    float* s_red   = s_wred + 128;          // 17

    const int tid  = threadIdx.x;
    const int row0 = blockIdx.x * TILE_M;

    // ---------------- Phase 0: cap / 1/cap / cap_sum partials / x tile ----------------
    {
        float v = cap[tid];                 // NCH == BDIM
        s_cap[tid]  = v;
        s_icap[tid] = 1.0f / v;
        #pragma unroll
        for (int off = 16; off; off >>= 1)
            v += __shfl_down_sync(0xffffffffu, v, off);
        if ((tid & 31) == 0) s_red[tid >> 5] = v;
    }
    const float4* xg = (const float4*)(x_cpm + (size_t)row0 * NCH);
    for (int idx = tid; idx < TILE_M * (NCH / 4); idx += BDIM) {
        int r = idx >> 7, c4 = idx & 127;
        *(float4*)(s_x + r * XS + c4 * 4) = xg[r * (NCH / 4) + c4];
    }
    __syncthreads();

    if (tid == 0) {
        float cs = 0.f;
        #pragma unroll
        for (int i = 0; i < 16; i++) cs += s_red[i];
        s_red[16] = cs;
    }

    // ---------------- Phase 1: raw dot(x_row, cap) ----------------
    // 32 k-slices x 16 row-groups of 4 rows: cap load amortized over 4 rows
    {
        int s = tid & 31, rgp1 = tid >> 5;
        const float4* cp = (const float4*)s_cap;
        float p0 = 0.f, p1 = 0.f, p2 = 0.f, p3 = 0.f;
        #pragma unroll
        for (int i4 = 0; i4 < 4; i4++) {
            int k4 = s + 32 * i4;
            float4 c = cp[k4];
            float4 a0 = ((const float4*)(s_x + (4 * rgp1 + 0) * XS))[k4];
            float4 a1 = ((const float4*)(s_x + (4 * rgp1 + 1) * XS))[k4];
            float4 a2 = ((const float4*)(s_x + (4 * rgp1 + 2) * XS))[k4];
            float4 a3 = ((const float4*)(s_x + (4 * rgp1 + 3) * XS))[k4];
            p0 = fmaf(a0.x, c.x, p0); p0 = fmaf(a0.y, c.y, p0); p0 = fmaf(a0.z, c.z, p0); p0 = fmaf(a0.w, c.w, p0);
            p1 = fmaf(a1.x, c.x, p1); p1 = fmaf(a1.y, c.y, p1); p1 = fmaf(a1.z, c.z, p1); p1 = fmaf(a1.w, c.w, p1);
            p2 = fmaf(a2.x, c.x, p2); p2 = fmaf(a2.y, c.y, p2); p2 = fmaf(a2.z, c.z, p2); p2 = fmaf(a2.w, c.w, p2);
            p3 = fmaf(a3.x, c.x, p3); p3 = fmaf(a3.y, c.y, p3); p3 = fmaf(a3.z, c.z, p3); p3 = fmaf(a3.w, c.w, p3);
        }
        #pragma unroll
        for (int off = 16; off; off >>= 1) {
            p0 += __shfl_down_sync(0xffffffffu, p0, off);
            p1 += __shfl_down_sync(0xffffffffu, p1, off);
            p2 += __shfl_down_sync(0xffffffffu, p2, off);
            p3 += __shfl_down_sync(0xffffffffu, p3, off);
        }
        if (s == 0) {
            s_eps[4 * rgp1 + 0] = p0;
            s_eps[4 * rgp1 + 1] = p1;
            s_eps[4 * rgp1 + 2] = p2;
            s_eps[4 * rgp1 + 3] = p3;
        }
    }
    __syncthreads();
    const float cap_sum = s_red[16];
    if (tid < TILE_M)
        s_eps[tid] = x_cons[row0 + tid] - s_eps[tid] / cap_sum;   // epsilon
    // (ordered before GEMM1 epilogue by the chunk-loop barriers)

    // ---------------- Phase 2: GEMM1  h1 = relu([x,eps] @ W1^T + b1) ----------------
    // R4-exact numerics: 2 rows x 4 cols per thread, sequential k 0..511 per output.
    const int cg = tid & 15;
    const int rg = tid >> 4;
    float acc0[4] = {0.f, 0.f, 0.f, 0.f};
    float acc1[4] = {0.f, 0.f, 0.f, 0.f};

    for (int kc = 0; kc < NCH; kc += 128) {
        __syncthreads();
        const float4* wsrc = (const float4*)(g_w1t + kc * 64);
        for (int i = tid; i < 2048; i += BDIM)
            ((float4*)s_w)[i] = wsrc[i];
        __syncthreads();

        const float* x0p = s_x + (2 * rg) * XS + kc;
        const float* x1p = x0p + XS;
        const float* wp  = s_w + 4 * cg;
        #pragma unroll 4
        for (int kk = 0; kk < 128; kk += 4) {
            float4 a0 = *(const float4*)(x0p + kk);
            float4 a1 = *(const float4*)(x1p + kk);
            float4 w0 = *(const float4*)(wp + (kk + 0) * 64);
            float4 w1 = *(const float4*)(wp + (kk + 1) * 64);
            float4 w2 = *(const float4*)(wp + (kk + 2) * 64);
            float4 w3 = *(const float4*)(wp + (kk + 3) * 64);
            fma4(acc0, a0.x, w0); fma4(acc0, a0.y, w1);
            fma4(acc0, a0.z, w2); fma4(acc0, a0.w, w3);
            fma4(acc1, a1.x, w0); fma4(acc1, a1.y, w1);
            fma4(acc1, a1.z, w2); fma4(acc1, a1.w, w3);
        }
    }
    {
        float4 we = *(const float4*)(g_w1t + 512 * 64 + 4 * cg);  // epsilon column
        float4 bb = *(const float4*)(b1 + 4 * cg);
        float e0 = s_eps[2 * rg], e1 = s_eps[2 * rg + 1];
        float4 h0, h1v;
        h0.x  = fmaxf(acc0[0] + e0 * we.x + bb.x, 0.f);
        h0.y  = fmaxf(acc0[1] + e0 * we.y + bb.y, 0.f);
        h0.z  = fmaxf(acc0[2] + e0 * we.z + bb.z, 0.f);
        h0.w  = fmaxf(acc0[3] + e0 * we.w + bb.w, 0.f);
        h1v.x = fmaxf(acc1[0] + e1 * we.x + bb.x, 0.f);
        h1v.y = fmaxf(acc1[1] + e1 * we.y + bb.y, 0.f);
        h1v.z = fmaxf(acc1[2] + e1 * we.z + bb.z, 0.f);
        h1v.w = fmaxf(acc1[3] + e1 * we.w + bb.w, 0.f);
        *(float4*)(s_h1 + (2 * rg)     * HS + 4 * cg) = h0;
        *(float4*)(s_h1 + (2 * rg + 1) * HS + 4 * cg) = h1v;
    }

    // ---------------- Phase 3: GEMM2 (8 rows x 4 cols, 256-col chunks) + tanh ----------------
    // per-output k-order: sequential 0..63 (identical to R4)
    const int cg2 = tid & 63;   // 4-col group within 256-col chunk
    const int rg2 = tid >> 6;   // 8-row group (warp-uniform -> broadcast h loads)
    float rsum[8];
    #pragma unroll
    for (int i = 0; i < 8; i++) rsum[i] = 0.f;

    for (int nc = 0; nc < NCH; nc += 256) {
        __syncthreads();
        // stage w2 chunk: 64k x 256 cols, stride 260 floats (65 float4)
        for (int i = tid; i < 4096; i += BDIM) {
            int k = i >> 6, c4 = i & 63;
            ((float4*)s_w)[k * WS2F4 + c4] =
                *(const float4*)(g_w2t + k * 512 + nc + 4 * c4);
        }
        __syncthreads();

        float a2[8][4];
        #pragma unroll
        for (int i = 0; i < 8; i++)
            #pragma unroll
            for (int j = 0; j < 4; j++) a2[i][j] = 0.f;

        const float4* wp = ((const float4*)s_w) + cg2;
        const float*  hb = s_h1 + (8 * rg2) * HS;
        #pragma unroll 2
        for (int kk = 0; kk < HID; kk += 4) {
            float4 w0 = wp[(kk + 0) * WS2F4];
            float4 w1 = wp[(kk + 1) * WS2F4];
            float4 w2 = wp[(kk + 2) * WS2F4];
            float4 w3 = wp[(kk + 3) * WS2F4];
            #pragma unroll
            for (int i = 0; i < 8; i++) {
                float4 h = *(const float4*)(hb + i * HS + kk);
                fma4(a2[i], h.x, w0); fma4(a2[i], h.y, w1);
                fma4(a2[i], h.z, w2); fma4(a2[i], h.w, w3);
            }
        }

        float4 bbv = *(const float4*)(b2 + nc + 4 * cg2);
        #pragma unroll
        for (int i = 0; i < 8; i++) {
            float4 tv;
            tv.x = fast_tanh(a2[i][0] + bbv.x);
            tv.y = fast_tanh(a2[i][1] + bbv.y);
            tv.z = fast_tanh(a2[i][2] + bbv.z);
            tv.w = fast_tanh(a2[i][3] + bbv.w);
            rsum[i] += (tv.x + tv.y) + (tv.z + tv.w);
            *(float4*)(s_x + (8 * rg2 + i) * XS + nc + 4 * cg2) = tv;
        }
    }

    // row sums: warp-local reduce (all lanes share rg2), 2 warps per rg2 combined via smem
    #pragma unroll
    for (int i = 0; i < 8; i++) {
        float v = rsum[i];
        #pragma unroll
        for (int off = 16; off; off >>= 1)
            v += __shfl_down_sync(0xffffffffu, v, off);
        if ((tid & 31) == 0) s_wred[(tid >> 5) * 8 + i] = v;
    }
    __syncthreads();
    if (tid < TILE_M) {
        int rg8 = tid >> 3, i = tid & 7;   // row = 8*rg8 + i == tid
        float tot = s_wred[(2 * rg8) * 8 + i] + s_wred[(2 * rg8 + 1) * 8 + i];
        s_scale[tid] = s_eps[tid] * cap_sum / tot;
    }
    __syncthreads();

    // ---------------- Phase 4: out = x + tanh * scale / cap ----------------
    float4* og = (float4*)(out + (size_t)row0 * NCH);
    for (int idx = tid; idx < TILE_M * (NCH / 4); idx += BDIM) {
        int r = idx >> 7, c4 = idx & 127;
        float4 xv = xg[r * (NCH / 4) + c4];
        float4 tv = *(const float4*)(s_x + r * XS + c4 * 4);
        float4 ic = *(const float4*)(s_icap + c4 * 4);
        float  sc = s_scale[r];
        float4 o;
        o.x = fmaf(tv.x * sc, ic.x, xv.x);
        o.y = fmaf(tv.y * sc, ic.y, xv.y);
        o.z = fmaf(tv.z * sc, ic.z, xv.z);
        o.w = fmaf(tv.w * sc, ic.w, xv.w);
        og[r * (NCH / 4) + c4] = o;
    }
}

static constexpr size_t SMEM_BYTES =
    (size_t)(N_SX + N_SW + N_SH1 + 512 + 512 + 64 + 64 + 128 + 17) * sizeof(float);

extern "C" void kernel_launch(void* const* d_in, const int* in_sizes, int n_in,
                              void* d_out, int out_size) {
    const float* x_cpm  = (const float*)d_in[0];
    const float* x_cons = (const float*)d_in[1];
    const float* cap    = (const float*)d_in[2];
    const float* b1     = (const float*)d_in[4];
    const float* W1     = (const float*)d_in[3];
    const float* W2     = (const float*)d_in[5];
    const float* b2     = (const float*)d_in[6];
    float* out = (float*)d_out;

    cudaFuncSetAttribute(fused_kernel, cudaFuncAttributeMaxDynamicSharedMemorySize,
                         (int)SMEM_BYTES);

    prep_kernel<<<129, 256>>>(W1, W2);

    const int B = 65536;
    fused_kernel<<<B / TILE_M, BDIM, SMEM_BYTES>>>(x_cpm, x_cons, cap, b1, b2, out);
}

// round 7
// speedup vs baseline: 1.0022x; 1.0022x over previous
#include <cuda_runtime.h>

#define BDIM   512
#define TILE_M 64
#define NCH    512
#define HID    64
#define XS     516   // x/tanh smem row stride (floats)
#define HS     68    // h1 smem row stride
#define WS2F4  65    // w2 stage row stride in float4 units (260 floats)

// Pre-transposed weights (written by prep_kernel each launch; deterministic).
__device__ __align__(16) float g_w1t[513 * 64];   // w1t[k][h] = W1[h][k], k=512 = epsilon column
__device__ __align__(16) float g_w2t[64 * 512];   // w2t[h][n] = W2[n][h]

__global__ void prep_kernel(const float* __restrict__ W1, const float* __restrict__ W2) {
    int idx = blockIdx.x * blockDim.x + threadIdx.x;
    if (idx < 513 * 64) {
        int k = idx >> 6, h = idx & 63;
        g_w1t[idx] = W1[h * 513 + k];
    }
    if (idx < 64 * 512) {
        int h = idx >> 9, n = idx & 511;
        g_w2t[idx] = W2[n * 64 + h];
    }
}

__device__ __forceinline__ float fast_tanh(float x) {
    float ax = fabsf(x);
    float e  = __expf(-2.0f * ax);
    float t  = __fdividef(1.0f - e, 1.0f + e);
    return copysignf(t, x);
}

__device__ __forceinline__ void fma4(float* acc, float a, float4 wv) {
    acc[0] = fmaf(a, wv.x, acc[0]);
    acc[1] = fmaf(a, wv.y, acc[1]);
    acc[2] = fmaf(a, wv.z, acc[2]);
    acc[3] = fmaf(a, wv.w, acc[3]);
}

// smem float counts
#define N_SX   (TILE_M * XS)      // 33024
#define N_SW   16640              // max(w1 stage 8192, w2 stage 64*260=16640)
#define N_SH1  (TILE_M * HS)      // 4352

__global__ __launch_bounds__(BDIM, 1)
void fused_kernel(const float* __restrict__ x_cpm,
                  const float* __restrict__ x_cons,
                  const float* __restrict__ cap,
                  const float* __restrict__ b1,
                  const float* __restrict__ b2,
                  float* __restrict__ out) {
    extern __shared__ float sm[];
    float* s_x     = sm;                    // x tile, later tanh buffer
    float* s_w     = s_x + N_SX;            // weight stage
    float* s_h1    = s_w + N_SW;
    float* s_cap   = s_h1 + N_SH1;          // 512
    float* s_icap  = s_cap + 512;           // 512
    float* s_eps   = s_icap + 512;          // 64
    float* s_scale = s_eps + 64;            // 64
    float* s_wred  = s_scale + 64;          // 128
    float* s_red   = s_wred + 128;          // 17

    const int tid  = threadIdx.x;
    const int row0 = blockIdx.x * TILE_M;

    // ---------------- Phase 0: cap / 1/cap / cap_sum partials / x tile ----------------
    {
        float v = cap[tid];                 // NCH == BDIM
        s_cap[tid]  = v;
        s_icap[tid] = 1.0f / v;
        #pragma unroll
        for (int off = 16; off; off >>= 1)
            v += __shfl_down_sync(0xffffffffu, v, off);
        if ((tid & 31) == 0) s_red[tid >> 5] = v;
    }
    const float4* xg = (const float4*)(x_cpm + (size_t)row0 * NCH);
    for (int idx = tid; idx < TILE_M * (NCH / 4); idx += BDIM) {
        int r = idx >> 7, c4 = idx & 127;
        *(float4*)(s_x + r * XS + c4 * 4) = xg[r * (NCH / 4) + c4];
    }
    __syncthreads();

    if (tid == 0) {
        float cs = 0.f;
        #pragma unroll
        for (int i = 0; i < 16; i++) cs += s_red[i];
        s_red[16] = cs;
    }

    // ---------------- Phase 1: raw dot(x_row, cap) ----------------
    // 32 k-slices x 16 row-groups of 4 rows: cap load amortized over 4 rows
    {
        int s = tid & 31, rgp1 = tid >> 5;
        const float4* cp = (const float4*)s_cap;
        float p0 = 0.f, p1 = 0.f, p2 = 0.f, p3 = 0.f;
        #pragma unroll
        for (int i4 = 0; i4 < 4; i4++) {
            int k4 = s + 32 * i4;
            float4 c = cp[k4];
            float4 a0 = ((const float4*)(s_x + (4 * rgp1 + 0) * XS))[k4];
            float4 a1 = ((const float4*)(s_x + (4 * rgp1 + 1) * XS))[k4];
            float4 a2 = ((const float4*)(s_x + (4 * rgp1 + 2) * XS))[k4];
            float4 a3 = ((const float4*)(s_x + (4 * rgp1 + 3) * XS))[k4];
            p0 = fmaf(a0.x, c.x, p0); p0 = fmaf(a0.y, c.y, p0); p0 = fmaf(a0.z, c.z, p0); p0 = fmaf(a0.w, c.w, p0);
            p1 = fmaf(a1.x, c.x, p1); p1 = fmaf(a1.y, c.y, p1); p1 = fmaf(a1.z, c.z, p1); p1 = fmaf(a1.w, c.w, p1);
            p2 = fmaf(a2.x, c.x, p2); p2 = fmaf(a2.y, c.y, p2); p2 = fmaf(a2.z, c.z, p2); p2 = fmaf(a2.w, c.w, p2);
            p3 = fmaf(a3.x, c.x, p3); p3 = fmaf(a3.y, c.y, p3); p3 = fmaf(a3.z, c.z, p3); p3 = fmaf(a3.w, c.w, p3);
        }
        #pragma unroll
        for (int off = 16; off; off >>= 1) {
            p0 += __shfl_down_sync(0xffffffffu, p0, off);
            p1 += __shfl_down_sync(0xffffffffu, p1, off);
            p2 += __shfl_down_sync(0xffffffffu, p2, off);
            p3 += __shfl_down_sync(0xffffffffu, p3, off);
        }
        if (s == 0) {
            s_eps[4 * rgp1 + 0] = p0;
            s_eps[4 * rgp1 + 1] = p1;
            s_eps[4 * rgp1 + 2] = p2;
            s_eps[4 * rgp1 + 3] = p3;
        }
    }
    __syncthreads();
    const float cap_sum = s_red[16];
    if (tid < TILE_M)
        s_eps[tid] = x_cons[row0 + tid] - s_eps[tid] / cap_sum;   // epsilon
    // (ordered before GEMM1 epilogue by the chunk-loop barriers)

    // ---------------- Phase 2: GEMM1  h1 = relu([x,eps] @ W1^T + b1) ----------------
    // R4-exact numerics: 2 rows x 4 cols per thread, sequential k 0..511 per output.
    const int cg = tid & 15;
    const int rg = tid >> 4;
    float acc0[4] = {0.f, 0.f, 0.f, 0.f};
    float acc1[4] = {0.f, 0.f, 0.f, 0.f};

    for (int kc = 0; kc < NCH; kc += 128) {
        __syncthreads();
        const float4* wsrc = (const float4*)(g_w1t + kc * 64);
        for (int i = tid; i < 2048; i += BDIM)
            ((float4*)s_w)[i] = wsrc[i];
        __syncthreads();

        const float* x0p = s_x + (2 * rg) * XS + kc;
        const float* x1p = x0p + XS;
        const float* wp  = s_w + 4 * cg;
        #pragma unroll 4
        for (int kk = 0; kk < 128; kk += 4) {
            float4 a0 = *(const float4*)(x0p + kk);
            float4 a1 = *(const float4*)(x1p + kk);
            float4 w0 = *(const float4*)(wp + (kk + 0) * 64);
            float4 w1 = *(const float4*)(wp + (kk + 1) * 64);
            float4 w2 = *(const float4*)(wp + (kk + 2) * 64);
            float4 w3 = *(const float4*)(wp + (kk + 3) * 64);
            fma4(acc0, a0.x, w0); fma4(acc0, a0.y, w1);
            fma4(acc0, a0.z, w2); fma4(acc0, a0.w, w3);
            fma4(acc1, a1.x, w0); fma4(acc1, a1.y, w1);
            fma4(acc1, a1.z, w2); fma4(acc1, a1.w, w3);
        }
    }
    {
        float4 we = *(const float4*)(g_w1t + 512 * 64 + 4 * cg);  // epsilon column
        float4 bb = *(const float4*)(b1 + 4 * cg);
        float e0 = s_eps[2 * rg], e1 = s_eps[2 * rg + 1];
        float4 h0, h1v;
        h0.x  = fmaxf(acc0[0] + e0 * we.x + bb.x, 0.f);
        h0.y  = fmaxf(acc0[1] + e0 * we.y + bb.y, 0.f);
        h0.z  = fmaxf(acc0[2] + e0 * we.z + bb.z, 0.f);
        h0.w  = fmaxf(acc0[3] + e0 * we.w + bb.w, 0.f);
        h1v.x = fmaxf(acc1[0] + e1 * we.x + bb.x, 0.f);
        h1v.y = fmaxf(acc1[1] + e1 * we.y + bb.y, 0.f);
        h1v.z = fmaxf(acc1[2] + e1 * we.z + bb.z, 0.f);
        h1v.w = fmaxf(acc1[3] + e1 * we.w + bb.w, 0.f);
        *(float4*)(s_h1 + (2 * rg)     * HS + 4 * cg) = h0;
        *(float4*)(s_h1 + (2 * rg + 1) * HS + 4 * cg) = h1v;
    }

    // ---------------- Phase 3: GEMM2 (8 rows x 4 cols, 256-col chunks) + tanh ----------------
    // per-output k-order: sequential 0..63 (identical to R4)
    const int cg2 = tid & 63;   // 4-col group within 256-col chunk
    const int rg2 = tid >> 6;   // 8-row group (warp-uniform -> broadcast h loads)
    float rsum[8];
    #pragma unroll
    for (int i = 0; i < 8; i++) rsum[i] = 0.f;

    for (int nc = 0; nc < NCH; nc += 256) {
        __syncthreads();
        // stage w2 chunk: 64k x 256 cols, stride 260 floats (65 float4)
        for (int i = tid; i < 4096; i += BDIM) {
            int k = i >> 6, c4 = i & 63;
            ((float4*)s_w)[k * WS2F4 + c4] =
                *(const float4*)(g_w2t + k * 512 + nc + 4 * c4);
        }
        __syncthreads();

        float a2[8][4];
        #pragma unroll
        for (int i = 0; i < 8; i++)
            #pragma unroll
            for (int j = 0; j < 4; j++) a2[i][j] = 0.f;

        const float4* wp = ((const float4*)s_w) + cg2;
        const float*  hb = s_h1 + (8 * rg2) * HS;
        #pragma unroll 2
        for (int kk = 0; kk < HID; kk += 4) {
            float4 w0 = wp[(kk + 0) * WS2F4];
            float4 w1 = wp[(kk + 1) * WS2F4];
            float4 w2 = wp[(kk + 2) * WS2F4];
            float4 w3 = wp[(kk + 3) * WS2F4];
            #pragma unroll
            for (int i = 0; i < 8; i++) {
                float4 h = *(const float4*)(hb + i * HS + kk);
                fma4(a2[i], h.x, w0); fma4(a2[i], h.y, w1);
                fma4(a2[i], h.z, w2); fma4(a2[i], h.w, w3);
            }
        }

        float4 bbv = *(const float4*)(b2 + nc + 4 * cg2);
        #pragma unroll
        for (int i = 0; i < 8; i++) {
            float4 tv;
            tv.x = fast_tanh(a2[i][0] + bbv.x);
            tv.y = fast_tanh(a2[i][1] + bbv.y);
            tv.z = fast_tanh(a2[i][2] + bbv.z);
            tv.w = fast_tanh(a2[i][3] + bbv.w);
            rsum[i] += (tv.x + tv.y) + (tv.z + tv.w);
            *(float4*)(s_x + (8 * rg2 + i) * XS + nc + 4 * cg2) = tv;
        }
    }

    // row sums: warp-local reduce (all lanes share rg2), 2 warps per rg2 combined via smem
    #pragma unroll
    for (int i = 0; i < 8; i++) {
        float v = rsum[i];
        #pragma unroll
        for (int off = 16; off; off >>= 1)
            v += __shfl_down_sync(0xffffffffu, v, off);
        if ((tid & 31) == 0) s_wred[(tid >> 5) * 8 + i] = v;
    }
    __syncthreads();
    if (tid < TILE_M) {
        int rg8 = tid >> 3, i = tid & 7;   // row = 8*rg8 + i == tid
        float tot = s_wred[(2 * rg8) * 8 + i] + s_wred[(2 * rg8 + 1) * 8 + i];
        s_scale[tid] = s_eps[tid] * cap_sum / tot;
    }
    __syncthreads();

    // ---------------- Phase 4: out = x + tanh * scale / cap ----------------
    float4* og = (float4*)(out + (size_t)row0 * NCH);
    for (int idx = tid; idx < TILE_M * (NCH / 4); idx += BDIM) {
        int r = idx >> 7, c4 = idx & 127;
        float4 xv = xg[r * (NCH / 4) + c4];
        float4 tv = *(const float4*)(s_x + r * XS + c4 * 4);
        float4 ic = *(const float4*)(s_icap + c4 * 4);
        float  sc = s_scale[r];
        float4 o;
        o.x = fmaf(tv.x * sc, ic.x, xv.x);
        o.y = fmaf(tv.y * sc, ic.y, xv.y);
        o.z = fmaf(tv.z * sc, ic.z, xv.z);
        o.w = fmaf(tv.w * sc, ic.w, xv.w);
        og[r * (NCH / 4) + c4] = o;
    }
}

static constexpr size_t SMEM_BYTES =
    (size_t)(N_SX + N_SW + N_SH1 + 512 + 512 + 64 + 64 + 128 + 17) * sizeof(float);

extern "C" void kernel_launch(void* const* d_in, const int* in_sizes, int n_in,
                              void* d_out, int out_size) {
    const float* x_cpm  = (const float*)d_in[0];
    const float* x_cons = (const float*)d_in[1];
    const float* cap    = (const float*)d_in[2];
    const float* b1     = (const float*)d_in[4];
    const float* W1     = (const float*)d_in[3];
    const float* W2     = (const float*)d_in[5];
    const float* b2     = (const float*)d_in[6];
    float* out = (float*)d_out;

    cudaFuncSetAttribute(fused_kernel, cudaFuncAttributeMaxDynamicSharedMemorySize,
                         (int)SMEM_BYTES);

    prep_kernel<<<129, 256>>>(W1, W2);

    const int B = 65536;
    fused_kernel<<<B / TILE_M, BDIM, SMEM_BYTES>>>(x_cpm, x_cons, cap, b1, b2, out);
}

// round 13
// speedup vs baseline: 1.1115x; 1.1091x over previous
#include <cuda_runtime.h>
#include <cstdint>

#define BDIM   512
#define TILE_M 128
#define NCH    512
#define HID    64
#define XBS    68     // x chunk row stride (floats)
#define HS     68     // h1 row stride
#define W2F4   65     // w2 stage row stride in float4 (260 floats)

// ---- smem float offsets ----
#define F_RED   0       // 17
#define F_CAP   32      // 512
#define F_ICAP  544     // 512
#define F_EPS   1056    // 128
#define F_SCALE 1184    // 128
#define F_RS    1312    // 128
#define F_OV    1440    // overlay: x buf (128*68=8704) + w1 buf (64*64=4096) | w2 stage (64*260=16640)
#define F_H1    18080   // 128*68 = 8704
#define SMEM_FLOATS 26784
#define SMEM_BYTES  (SMEM_FLOATS * 4)   // 107136

// Pre-transposed weights (R4 prep, unchanged values).
__device__ __align__(16) float g_w1t[513 * 64];   // [k][h], k=512 = epsilon column
__device__ __align__(16) float g_w2t[64 * 512];   // [k][n]
// tanh scratch (fp32, exact)
__device__ float g_t[65536 * 512];

__global__ void prep_kernel(const float* __restrict__ W1, const float* __restrict__ W2) {
    int idx = blockIdx.x * blockDim.x + threadIdx.x;
    if (idx < 513 * 64) {
        int k = idx >> 6, h = idx & 63;
        g_w1t[idx] = W1[h * 513 + k];
    }
    if (idx < 64 * 512) {
        int h = idx >> 9, n = idx & 511;
        g_w2t[idx] = W2[n * 64 + h];
    }
}

__device__ __forceinline__ float fast_tanh(float x) {
    float ax = fabsf(x);
    float e  = __expf(-2.0f * ax);
    float t  = __fdividef(1.0f - e, 1.0f + e);
    return copysignf(t, x);
}

__device__ __forceinline__ void fma4(float* acc, float a, float4 wv) {
    acc[0] = fmaf(a, wv.x, acc[0]);
    acc[1] = fmaf(a, wv.y, acc[1]);
    acc[2] = fmaf(a, wv.z, acc[2]);
    acc[3] = fmaf(a, wv.w, acc[3]);
}

__global__ __launch_bounds__(BDIM, 1)
void fused_kernel(const float* __restrict__ x_cpm,
                  const float* __restrict__ x_cons,
                  const float* __restrict__ cap,
                  const float* __restrict__ b1,
                  const float* __restrict__ b2,
                  float* __restrict__ out) {
    extern __shared__ float sm[];
    const int tid  = threadIdx.x;
    const int row0 = blockIdx.x * TILE_M;
    float* s_xb = sm + F_OV;          // x chunk [128][68]
    float* s_wb = sm + F_OV + 8704;   // w1 chunk [64][64]
    float* s_h1 = sm + F_H1;

    // ---------------- P0: constants ----------------
    {
        float v = cap[tid];
        sm[F_CAP + tid]  = v;
        sm[F_ICAP + tid] = 1.0f / v;
        #pragma unroll
        for (int off = 16; off; off >>= 1)
            v += __shfl_down_sync(0xffffffffu, v, off);
        if ((tid & 31) == 0) sm[F_RED + (tid >> 5)] = v;
    }
    __syncthreads();
    if (tid == 0) {
        float cs = 0.f;
        #pragma unroll
        for (int i = 0; i < 16; i++) cs += sm[F_RED + i];
        sm[F_RED + 16] = cs;
    }

    // ---------------- P1: 8 k-chunks — stage x + w1, eps partial, GEMM1 ----------------
    const int es = tid & 3;      // eps k-slot (R4 order)
    const int er = tid >> 2;     // eps row 0..127
    const int cg = tid & 15;     // GEMM1 col group (4 cols)
    const int rg = tid >> 4;     // GEMM1 row group (4 rows), 0..31
    float pe = 0.f;
    float acc[4][4];
    #pragma unroll
    for (int i = 0; i < 4; i++)
        #pragma unroll
        for (int j = 0; j < 4; j++) acc[i][j] = 0.f;

    const float4* xg = (const float4*)(x_cpm + (size_t)row0 * NCH);

    for (int c = 0; c < 8; c++) {
        __syncthreads();   // prior chunk's reads complete
        // stage x chunk: 2048 float4 (row-major 16 f4 per row)
        #pragma unroll
        for (int j = 0; j < 4; j++) {
            int idx = tid + j * BDIM;
            int r = idx >> 4, c16 = idx & 15;
            *(float4*)(s_xb + r * XBS + 4 * c16) = xg[r * 128 + c * 16 + c16];
        }
        // stage w1 chunk: 1024 float4
        #pragma unroll
        for (int j = 0; j < 2; j++) {
            int idx = tid + j * BDIM;
            int kk = idx >> 4, h4 = idx & 15;
            *(float4*)(s_wb + kk * 64 + 4 * h4) =
                ((const float4*)(g_w1t + (c * 64 + kk) * 64))[h4];
        }
        __syncthreads();

        // eps partial — R4-exact order: k = 64c + es + 4i, i ascending
        {
            const float* xr = s_xb + er * XBS;
            const float* cp = sm + F_CAP + c * 64;
            #pragma unroll 4
            for (int i = 0; i < 16; i++) {
                int k = es + 4 * i;
                pe = fmaf(xr[k], cp[k], pe);
            }
        }
        // GEMM1: 4 rows x 4 cols, kk ascending
        {
            const float* xb = s_xb + (4 * rg) * XBS;
            const float* wp = s_wb + 4 * cg;
            #pragma unroll 4
            for (int kk = 0; kk < 64; kk += 4) {
                float4 w0 = *(const float4*)(wp + (kk + 0) * 64);
                float4 w1 = *(const float4*)(wp + (kk + 1) * 64);
                float4 w2 = *(const float4*)(wp + (kk + 2) * 64);
                float4 w3 = *(const float4*)(wp + (kk + 3) * 64);
                #pragma unroll
                for (int r = 0; r < 4; r++) {
                    float4 a = *(const float4*)(xb + r * XBS + kk);
                    fma4(acc[r], a.x, w0); fma4(acc[r], a.y, w1);
                    fma4(acc[r], a.z, w2); fma4(acc[r], a.w, w3);
                }
            }
        }
    }

    // ---------------- P2: epsilon (R4-exact reduction) ----------------
    pe += __shfl_down_sync(0xffffffffu, pe, 2, 4);
    pe += __shfl_down_sync(0xffffffffu, pe, 1, 4);
    if (es == 0) sm[F_EPS + er] = pe;
    __syncthreads();
    const float cap_sum = sm[F_RED + 16];
    if (tid < TILE_M)
        sm[F_EPS + tid] = x_cons[row0 + tid] - sm[F_EPS + tid] / cap_sum;
    __syncthreads();

    // ---------------- P3: GEMM1 epilogue -> h1 ----------------
    {
        float4 we = *(const float4*)(g_w1t + 512 * 64 + 4 * cg);
        float4 bb = *(const float4*)(b1 + 4 * cg);
        #pragma unroll
        for (int r = 0; r < 4; r++) {
            float e = sm[F_EPS + 4 * rg + r];
            float4 h;
            h.x = fmaxf(acc[r][0] + e * we.x + bb.x, 0.f);
            h.y = fmaxf(acc[r][1] + e * we.y + bb.y, 0.f);
            h.z = fmaxf(acc[r][2] + e * we.z + bb.z, 0.f);
            h.w = fmaxf(acc[r][3] + e * we.w + bb.w, 0.f);
            *(float4*)(s_h1 + (4 * rg + r) * HS + 4 * cg) = h;
        }
    }

    // ---------------- P4: GEMM2 in 2 chunks of 256 cols + tanh -> g_t ----------------
    const int cg2 = tid & 31;    // 4 cols at 4cg2, 4 cols at 128+4cg2
    const int rg2 = tid >> 5;    // == warp id; rows 8rg2..8rg2+7
    float rs[8];
    #pragma unroll
    for (int i = 0; i < 8; i++) rs[i] = 0.f;

    for (int nc = 0; nc < NCH; nc += 256) {
        __syncthreads();
        // stage w2 chunk into overlay: [64 k][260]
        #pragma unroll
        for (int j = 0; j < 8; j++) {
            int idx = tid + j * BDIM;
            int kk = idx >> 6, c4 = idx & 63;
            ((float4*)(sm + F_OV))[kk * W2F4 + c4] =
                ((const float4*)(g_w2t + kk * 512 + nc))[c4];
        }
        __syncthreads();

        float aA[8][4], aB[8][4];
        #pragma unroll
        for (int r = 0; r < 8; r++)
            #pragma unroll
            for (int j = 0; j < 4; j++) { aA[r][j] = 0.f; aB[r][j] = 0.f; }

        const float4* wp = ((const float4*)(sm + F_OV)) + cg2;
        const float*  hb = s_h1 + (8 * rg2) * HS;
        #pragma unroll 2
        for (int kk = 0; kk < HID; kk += 4) {
            float4 wA0 = wp[(kk + 0) * W2F4], wB0 = wp[(kk + 0) * W2F4 + 32];
            float4 wA1 = wp[(kk + 1) * W2F4], wB1 = wp[(kk + 1) * W2F4 + 32];
            float4 wA2 = wp[(kk + 2) * W2F4], wB2 = wp[(kk + 2) * W2F4 + 32];
            float4 wA3 = wp[(kk + 3) * W2F4], wB3 = wp[(kk + 3) * W2F4 + 32];
            #pragma unroll
            for (int r = 0; r < 8; r++) {
                float4 h = *(const float4*)(hb + r * HS + kk);   // broadcast (warp-uniform row)
                fma4(aA[r], h.x, wA0); fma4(aB[r], h.x, wB0);
                fma4(aA[r], h.y, wA1); fma4(aB[r], h.y, wB1);
                fma4(aA[r], h.z, wA2); fma4(aB[r], h.z, wB2);
                fma4(aA[r], h.w, wA3); fma4(aB[r], h.w, wB3);
            }
        }

        float4 bbA = *(const float4*)(b2 + nc + 4 * cg2);
        float4 bbB = *(const float4*)(b2 + nc + 128 + 4 * cg2);
        #pragma unroll
        for (int r = 0; r < 8; r++) {
            float4 tA, tB;
            tA.x = fast_tanh(aA[r][0] + bbA.x);
            tA.y = fast_tanh(aA[r][1] + bbA.y);
            tA.z = fast_tanh(aA[r][2] + bbA.z);
            tA.w = fast_tanh(aA[r][3] + bbA.w);
            tB.x = fast_tanh(aB[r][0] + bbB.x);
            tB.y = fast_tanh(aB[r][1] + bbB.y);
            tB.z = fast_tanh(aB[r][2] + bbB.z);
            tB.w = fast_tanh(aB[r][3] + bbB.w);
            rs[r] += ((tA.x + tA.y) + (tA.z + tA.w)) + ((tB.x + tB.y) + (tB.z + tB.w));
            float* dst = g_t + (size_t)(row0 + 8 * rg2 + r) * NCH + nc + 4 * cg2;
            *(float4*)(dst)       = tA;
            *(float4*)(dst + 128) = tB;
        }
    }

    // ---------------- P5: rowsums (one warp per 8 rows) -> scale ----------------
    #pragma unroll
    for (int r = 0; r < 8; r++) {
        float v = rs[r];
        #pragma unroll
        for (int off = 16; off; off >>= 1)
            v += __shfl_down_sync(0xffffffffu, v, off);
        if (cg2 == 0) sm[F_RS + 8 * rg2 + r] = v;
    }
    __syncthreads();
    if (tid < TILE_M)
        sm[F_SCALE + tid] = sm[F_EPS + tid] * cap_sum / sm[F_RS + tid];
    __syncthreads();

    // ---------------- P6: out = x + t * scale / cap ----------------
    for (int idx = tid; idx < TILE_M * (NCH / 4); idx += BDIM) {
        int r = idx >> 7, c4 = idx & 127;
        float4 xv = xg[r * 128 + c4];
        float4 tv = *(const float4*)(g_t + (size_t)(row0 + r) * NCH + 4 * c4);
        float4 ic = *(const float4*)(sm + F_ICAP + 4 * c4);
        float  sc = sm[F_SCALE + r];
        float4 o;
        o.x = fmaf(tv.x * sc, ic.x, xv.x);
        o.y = fmaf(tv.y * sc, ic.y, xv.y);
        o.z = fmaf(tv.z * sc, ic.z, xv.z);
        o.w = fmaf(tv.w * sc, ic.w, xv.w);
        *(float4*)(out + (size_t)(row0 + r) * NCH + 4 * c4) = o;
    }
}

extern "C" void kernel_launch(void* const* d_in, const int* in_sizes, int n_in,
                              void* d_out, int out_size) {
    const float* x_cpm  = (const float*)d_in[0];
    const float* x_cons = (const float*)d_in[1];
    const float* cap    = (const float*)d_in[2];
    const float* W1     = (const float*)d_in[3];
    const float* b1     = (const float*)d_in[4];
    const float* W2     = (const float*)d_in[5];
    const float* b2     = (const float*)d_in[6];
    float* out = (float*)d_out;

    cudaFuncSetAttribute(fused_kernel, cudaFuncAttributeMaxDynamicSharedMemorySize, SMEM_BYTES);

    prep_kernel<<<129, 256>>>(W1, W2);

    const int B = 65536;
    fused_kernel<<<B / TILE_M, BDIM, SMEM_BYTES>>>(x_cpm, x_cons, cap, b1, b2, out);
}

// round 15
// speedup vs baseline: 1.1581x; 1.0419x over previous
#include <cuda_runtime.h>
#include <cstdint>

#define BDIM   512
#define TILE_M 128
#define NCH    512
#define HID    64
#define XBS    68     // x chunk row stride (floats)
#define HS     68     // h1 row stride
#define W2F4   65     // w2 stage row stride in float4 (260 floats)

// ---- smem float offsets ----
#define F_RED   0       // 17
#define F_CAP   32      // 512
#define F_ICAP  544     // 512
#define F_EPS   1056    // 128
#define F_SCALE 1184    // 128
#define F_RS    1312    // 128
#define F_OV    1440    // overlay: x buf (8704) + w1 buf (4096) | w2 stage (16640)
#define F_H1    18080   // 128*68 = 8704
#define SMEM_FLOATS 26784
#define SMEM_BYTES  (SMEM_FLOATS * 4)   // 107136

// Pre-transposed weights.
__device__ __align__(16) float g_w1t[513 * 64];   // [k][h], k=512 = epsilon column
__device__ __align__(16) float g_w2t[64 * 512];   // [k][n]
// tanh scratch (fp32, exact)
__device__ float g_t[65536 * 512];

__global__ void prep_kernel(const float* __restrict__ W1, const float* __restrict__ W2) {
    int idx = blockIdx.x * blockDim.x + threadIdx.x;
    if (idx < 513 * 64) {
        int k = idx >> 6, h = idx & 63;
        g_w1t[idx] = W1[h * 513 + k];
    }
    if (idx < 64 * 512) {
        int h = idx >> 9, n = idx & 511;
        g_w2t[idx] = W2[n * 64 + h];
    }
}

__device__ __forceinline__ float fast_tanh(float x) {
    float ax = fabsf(x);
    float e  = __expf(-2.0f * ax);
    float t  = __fdividef(1.0f - e, 1.0f + e);
    return copysignf(t, x);
}

// ---- packed f32x2 helpers (FFMA2 path; each half is an exact IEEE fp32 FMA) ----
__device__ __forceinline__ void fma2(uint64_t& acc, uint64_t a, uint64_t b) {
    asm("fma.rn.f32x2 %0, %1, %2, %0;" : "+l"(acc) : "l"(a), "l"(b));
}
__device__ __forceinline__ uint64_t pk2(float x, float y) {
    uint64_t r;
    asm("mov.b64 %0, {%1, %2};" : "=l"(r) : "r"(__float_as_uint(x)), "r"(__float_as_uint(y)));
    return r;
}
__device__ __forceinline__ uint64_t bc2(float x) {
    uint64_t r;
    uint32_t u = __float_as_uint(x);
    asm("mov.b64 %0, {%1, %1};" : "=l"(r) : "r"(u));
    return r;
}
__device__ __forceinline__ float2 up2(uint64_t v) {
    uint32_t lo, hi;
    asm("mov.b64 {%0, %1}, %2;" : "=r"(lo), "=r"(hi) : "l"(v));
    return make_float2(__uint_as_float(lo), __uint_as_float(hi));
}

__global__ __launch_bounds__(BDIM, 1)
void fused_kernel(const float* __restrict__ x_cpm,
                  const float* __restrict__ x_cons,
                  const float* __restrict__ cap,
                  const float* __restrict__ b1,
                  const float* __restrict__ b2,
                  float* __restrict__ out) {
    extern __shared__ float sm[];
    const int tid  = threadIdx.x;
    const int row0 = blockIdx.x * TILE_M;
    float* s_xb = sm + F_OV;          // x chunk [128][68]
    float* s_wb = sm + F_OV + 8704;   // w1 chunk [64][64]
    float* s_h1 = sm + F_H1;

    // ---------------- P0: constants ----------------
    {
        float v = cap[tid];
        sm[F_CAP + tid]  = v;
        sm[F_ICAP + tid] = 1.0f / v;
        #pragma unroll
        for (int off = 16; off; off >>= 1)
            v += __shfl_down_sync(0xffffffffu, v, off);
        if ((tid & 31) == 0) sm[F_RED + (tid >> 5)] = v;
    }
    __syncthreads();
    if (tid == 0) {
        float cs = 0.f;
        #pragma unroll
        for (int i = 0; i < 16; i++) cs += sm[F_RED + i];
        sm[F_RED + 16] = cs;
    }

    // ---------------- P1: 8 k-chunks — stage x + w1, eps partial, GEMM1 ----------------
    const int es = tid & 3;
    const int er = tid >> 2;
    const int cg = tid & 15;     // col group (4 cols: pairs (0,1),(2,3))
    const int rg = tid >> 4;     // row group (4 rows)
    float pe = 0.f;
    uint64_t acc01[4] = {0, 0, 0, 0};   // cols 4cg+0,1
    uint64_t acc23[4] = {0, 0, 0, 0};   // cols 4cg+2,3

    const float4* xg = (const float4*)(x_cpm + (size_t)row0 * NCH);

    for (int c = 0; c < 8; c++) {
        __syncthreads();
        #pragma unroll
        for (int j = 0; j < 4; j++) {
            int idx = tid + j * BDIM;
            int r = idx >> 4, c16 = idx & 15;
            *(float4*)(s_xb + r * XBS + 4 * c16) = xg[r * 128 + c * 16 + c16];
        }
        #pragma unroll
        for (int j = 0; j < 2; j++) {
            int idx = tid + j * BDIM;
            int kk = idx >> 4, h4 = idx & 15;
            *(float4*)(s_wb + kk * 64 + 4 * h4) =
                ((const float4*)(g_w1t + (c * 64 + kk) * 64))[h4];
        }
        __syncthreads();

        // eps partial — R4-exact order
        {
            const float* xr = s_xb + er * XBS;
            const float* cp = sm + F_CAP + c * 64;
            #pragma unroll 4
            for (int i = 0; i < 16; i++) {
                int k = es + 4 * i;
                pe = fmaf(xr[k], cp[k], pe);
            }
        }
        // GEMM1: 4 rows x 4 cols (2 col-pairs), kk ascending, FFMA2
        {
            const float* xb = s_xb + (4 * rg) * XBS;
            const float* wp = s_wb + 4 * cg;
            #pragma unroll 4
            for (int kk = 0; kk < 64; kk += 4) {
                float4 w0 = *(const float4*)(wp + (kk + 0) * 64);
                float4 w1 = *(const float4*)(wp + (kk + 1) * 64);
                float4 w2 = *(const float4*)(wp + (kk + 2) * 64);
                float4 w3 = *(const float4*)(wp + (kk + 3) * 64);
                uint64_t w0a = pk2(w0.x, w0.y), w0b = pk2(w0.z, w0.w);
                uint64_t w1a = pk2(w1.x, w1.y), w1b = pk2(w1.z, w1.w);
                uint64_t w2a = pk2(w2.x, w2.y), w2b = pk2(w2.z, w2.w);
                uint64_t w3a = pk2(w3.x, w3.y), w3b = pk2(w3.z, w3.w);
                #pragma unroll
                for (int r = 0; r < 4; r++) {
                    float4 a = *(const float4*)(xb + r * XBS + kk);
                    uint64_t ax = bc2(a.x), ay = bc2(a.y);
                    uint64_t az = bc2(a.z), aw = bc2(a.w);
                    fma2(acc01[r], ax, w0a); fma2(acc23[r], ax, w0b);
                    fma2(acc01[r], ay, w1a); fma2(acc23[r], ay, w1b);
                    fma2(acc01[r], az, w2a); fma2(acc23[r], az, w2b);
                    fma2(acc01[r], aw, w3a); fma2(acc23[r], aw, w3b);
                }
            }
        }
    }

    // ---------------- P2: epsilon ----------------
    pe += __shfl_down_sync(0xffffffffu, pe, 2, 4);
    pe += __shfl_down_sync(0xffffffffu, pe, 1, 4);
    if (es == 0) sm[F_EPS + er] = pe;
    __syncthreads();
    const float cap_sum = sm[F_RED + 16];
    if (tid < TILE_M)
        sm[F_EPS + tid] = x_cons[row0 + tid] - sm[F_EPS + tid] / cap_sum;
    __syncthreads();

    // ---------------- P3: GEMM1 epilogue -> h1 ----------------
    {
        float4 we = *(const float4*)(g_w1t + 512 * 64 + 4 * cg);
        float4 bb = *(const float4*)(b1 + 4 * cg);
        #pragma unroll
        for (int r = 0; r < 4; r++) {
            float e = sm[F_EPS + 4 * rg + r];
            float2 c01 = up2(acc01[r]), c23 = up2(acc23[r]);
            float4 h;
            h.x = fmaxf(c01.x + e * we.x + bb.x, 0.f);
            h.y = fmaxf(c01.y + e * we.y + bb.y, 0.f);
            h.z = fmaxf(c23.x + e * we.z + bb.z, 0.f);
            h.w = fmaxf(c23.y + e * we.w + bb.w, 0.f);
            *(float4*)(s_h1 + (4 * rg + r) * HS + 4 * cg) = h;
        }
    }

    // ---------------- P4: GEMM2 in 2 chunks of 256 cols + tanh -> g_t ----------------
    const int cg2 = tid & 31;
    const int rg2 = tid >> 5;    // warp id; rows 8rg2..8rg2+7
    float rs[8];
    #pragma unroll
    for (int i = 0; i < 8; i++) rs[i] = 0.f;

    for (int nc = 0; nc < NCH; nc += 256) {
        __syncthreads();
        #pragma unroll
        for (int j = 0; j < 8; j++) {
            int idx = tid + j * BDIM;
            int kk = idx >> 6, c4 = idx & 63;
            ((float4*)(sm + F_OV))[kk * W2F4 + c4] =
                ((const float4*)(g_w2t + kk * 512 + nc))[c4];
        }
        __syncthreads();

        uint64_t aA01[8], aA23[8], aB01[8], aB23[8];
        #pragma unroll
        for (int r = 0; r < 8; r++) { aA01[r] = 0; aA23[r] = 0; aB01[r] = 0; aB23[r] = 0; }

        const float4* wp = ((const float4*)(sm + F_OV)) + cg2;
        const float*  hb = s_h1 + (8 * rg2) * HS;
        #pragma unroll 2
        for (int kk = 0; kk < HID; kk += 4) {
            float4 wA0 = wp[(kk + 0) * W2F4], wB0 = wp[(kk + 0) * W2F4 + 32];
            float4 wA1 = wp[(kk + 1) * W2F4], wB1 = wp[(kk + 1) * W2F4 + 32];
            float4 wA2 = wp[(kk + 2) * W2F4], wB2 = wp[(kk + 2) * W2F4 + 32];
            float4 wA3 = wp[(kk + 3) * W2F4], wB3 = wp[(kk + 3) * W2F4 + 32];
            uint64_t A0a = pk2(wA0.x, wA0.y), A0b = pk2(wA0.z, wA0.w);
            uint64_t A1a = pk2(wA1.x, wA1.y), A1b = pk2(wA1.z, wA1.w);
            uint64_t A2a = pk2(wA2.x, wA2.y), A2b = pk2(wA2.z, wA2.w);
            uint64_t A3a = pk2(wA3.x, wA3.y), A3b = pk2(wA3.z, wA3.w);
            uint64_t B0a = pk2(wB0.x, wB0.y), B0b = pk2(wB0.z, wB0.w);
            uint64_t B1a = pk2(wB1.x, wB1.y), B1b = pk2(wB1.z, wB1.w);
            uint64_t B2a = pk2(wB2.x, wB2.y), B2b = pk2(wB2.z, wB2.w);
            uint64_t B3a = pk2(wB3.x, wB3.y), B3b = pk2(wB3.z, wB3.w);
            #pragma unroll
            for (int r = 0; r < 8; r++) {
                float4 h = *(const float4*)(hb + r * HS + kk);   // broadcast
                uint64_t hx = bc2(h.x), hy = bc2(h.y), hz = bc2(h.z), hw = bc2(h.w);
                fma2(aA01[r], hx, A0a); fma2(aA23[r], hx, A0b);
                fma2(aB01[r], hx, B0a); fma2(aB23[r], hx, B0b);
                fma2(aA01[r], hy, A1a); fma2(aA23[r], hy, A1b);
                fma2(aB01[r], hy, B1a); fma2(aB23[r], hy, B1b);
                fma2(aA01[r], hz, A2a); fma2(aA23[r], hz, A2b);
                fma2(aB01[r], hz, B2a); fma2(aB23[r], hz, B2b);
                fma2(aA01[r], hw, A3a); fma2(aA23[r], hw, A3b);
                fma2(aB01[r], hw, B3a); fma2(aB23[r], hw, B3b);
            }
        }

        float4 bbA = *(const float4*)(b2 + nc + 4 * cg2);
        float4 bbB = *(const float4*)(b2 + nc + 128 + 4 * cg2);
        #pragma unroll
        for (int r = 0; r < 8; r++) {
            float2 a01 = up2(aA01[r]), a23 = up2(aA23[r]);
            float2 b01 = up2(aB01[r]), b23 = up2(aB23[r]);
            float4 tA, tB;
            tA.x = fast_tanh(a01.x + bbA.x);
            tA.y = fast_tanh(a01.y + bbA.y);
            tA.z = fast_tanh(a23.x + bbA.z);
            tA.w = fast_tanh(a23.y + bbA.w);
            tB.x = fast_tanh(b01.x + bbB.x);
            tB.y = fast_tanh(b01.y + bbB.y);
            tB.z = fast_tanh(b23.x + bbB.z);
            tB.w = fast_tanh(b23.y + bbB.w);
            rs[r] += ((tA.x + tA.y) + (tA.z + tA.w)) + ((tB.x + tB.y) + (tB.z + tB.w));
            float* dst = g_t + (size_t)(row0 + 8 * rg2 + r) * NCH + nc + 4 * cg2;
            *(float4*)(dst)       = tA;
            *(float4*)(dst + 128) = tB;
        }
    }

    // ---------------- P5: rowsums -> scale ----------------
    #pragma unroll
    for (int r = 0; r < 8; r++) {
        float v = rs[r];
        #pragma unroll
        for (int off = 16; off; off >>= 1)
            v += __shfl_down_sync(0xffffffffu, v, off);
        if (cg2 == 0) sm[F_RS + 8 * rg2 + r] = v;
    }
    __syncthreads();
    if (tid < TILE_M)
        sm[F_SCALE + tid] = sm[F_EPS + tid] * cap_sum / sm[F_RS + tid];
    __syncthreads();

    // ---------------- P6: out = x + t * scale / cap ----------------
    for (int idx = tid; idx < TILE_M * (NCH / 4); idx += BDIM) {
        int r = idx >> 7, c4 = idx & 127;
        float4 xv = xg[r * 128 + c4];
        float4 tv = *(const float4*)(g_t + (size_t)(row0 + r) * NCH + 4 * c4);
        float4 ic = *(const float4*)(sm + F_ICAP + 4 * c4);
        float  sc = sm[F_SCALE + r];
        float4 o;
        o.x = fmaf(tv.x * sc, ic.x, xv.x);
        o.y = fmaf(tv.y * sc, ic.y, xv.y);
        o.z = fmaf(tv.z * sc, ic.z, xv.z);
        o.w = fmaf(tv.w * sc, ic.w, xv.w);
        *(float4*)(out + (size_t)(row0 + r) * NCH + 4 * c4) = o;
    }
}

extern "C" void kernel_launch(void* const* d_in, const int* in_sizes, int n_in,
                              void* d_out, int out_size) {
    const float* x_cpm  = (const float*)d_in[0];
    const float* x_cons = (const float*)d_in[1];
    const float* cap    = (const float*)d_in[2];
    const float* W1     = (const float*)d_in[3];
    const float* b1     = (const float*)d_in[4];
    const float* W2     = (const float*)d_in[5];
    const float* b2     = (const float*)d_in[6];
    float* out = (float*)d_out;

    cudaFuncSetAttribute(fused_kernel, cudaFuncAttributeMaxDynamicSharedMemorySize, SMEM_BYTES);

    prep_kernel<<<129, 256>>>(W1, W2);

    const int B = 65536;
    fused_kernel<<<B / TILE_M, BDIM, SMEM_BYTES>>>(x_cpm, x_cons, cap, b1, b2, out);
}

// round 16
// speedup vs baseline: 1.3466x; 1.1627x over previous
#include <cuda_runtime.h>
#include <cstdint>

#define BDIM   256
#define TILE_M 64
#define NCH    512
#define HID    64
#define XBS    68     // x chunk row stride (floats)
#define HS     68     // h1 row stride
#define W2F4   33     // w2 stage row stride in float4 (132 floats)

// ---- smem float offsets ----
#define F_RED   0       // 17
#define F_CAP   32      // 512
#define F_ICAP  544     // 512
#define F_EPS   1056    // 64
#define F_SCALE 1120    // 64
#define F_RS    1184    // 64
#define F_OV    1248    // overlay: x buf (64*68=4352) + w1 buf (4096) | w2 stage (64*132=8448)
#define F_H1    9952    // 64*68 = 4352
#define SMEM_FLOATS 14304
#define SMEM_BYTES  (SMEM_FLOATS * 4)   // 57216

// Pre-transposed weights.
__device__ __align__(16) float g_w1t[513 * 64];   // [k][h], k=512 = epsilon column
__device__ __align__(16) float g_w2t[64 * 512];   // [k][n]
// tanh scratch (fp32, exact)
__device__ float g_t[65536 * 512];

__global__ void prep_kernel(const float* __restrict__ W1, const float* __restrict__ W2) {
    int idx = blockIdx.x * blockDim.x + threadIdx.x;
    if (idx < 513 * 64) {
        int k = idx >> 6, h = idx & 63;
        g_w1t[idx] = W1[h * 513 + k];
    }
    if (idx < 64 * 512) {
        int h = idx >> 9, n = idx & 511;
        g_w2t[idx] = W2[n * 64 + h];
    }
}

__device__ __forceinline__ float fast_tanh(float x) {
    float ax = fabsf(x);
    float e  = __expf(-2.0f * ax);
    float t  = __fdividef(1.0f - e, 1.0f + e);
    return copysignf(t, x);
}

__device__ __forceinline__ void fma4(float* acc, float a, float4 wv) {
    acc[0] = fmaf(a, wv.x, acc[0]);
    acc[1] = fmaf(a, wv.y, acc[1]);
    acc[2] = fmaf(a, wv.z, acc[2]);
    acc[3] = fmaf(a, wv.w, acc[3]);
}

__global__ __launch_bounds__(BDIM, 2)
void fused_kernel(const float* __restrict__ x_cpm,
                  const float* __restrict__ x_cons,
                  const float* __restrict__ cap,
                  const float* __restrict__ b1,
                  const float* __restrict__ b2,
                  float* __restrict__ out) {
    extern __shared__ float sm[];
    const int tid  = threadIdx.x;
    const int row0 = blockIdx.x * TILE_M;
    float* s_xb = sm + F_OV;          // x chunk [64][68]
    float* s_wb = sm + F_OV + 4352;   // w1 chunk [64][64]
    float* s_h1 = sm + F_H1;

    // ---------------- P0: constants ----------------
    {
        float v0 = cap[tid], v1 = cap[tid + 256];
        sm[F_CAP + tid]        = v0;
        sm[F_CAP + tid + 256]  = v1;
        sm[F_ICAP + tid]       = 1.0f / v0;
        sm[F_ICAP + tid + 256] = 1.0f / v1;
        float v = v0 + v1;   // pairwise; fp32-reorder class for cap_sum (non-amplified)
        #pragma unroll
        for (int off = 16; off; off >>= 1)
            v += __shfl_down_sync(0xffffffffu, v, off);
        if ((tid & 31) == 0) sm[F_RED + (tid >> 5)] = v;
    }
    __syncthreads();
    if (tid == 0) {
        float cs = 0.f;
        #pragma unroll
        for (int i = 0; i < 8; i++) cs += sm[F_RED + i];
        sm[F_RED + 16] = cs;
    }

    // ---------------- P1: 8 k-chunks — stage x + w1, eps partial, GEMM1 ----------------
    const int es = tid & 3;      // eps k-slot (R4 order)
    const int er = tid >> 2;     // eps row 0..63
    const int cg = tid & 15;     // GEMM1 col group (4 cols)
    const int rg = tid >> 4;     // GEMM1 row group (4 rows), 0..15
    float pe = 0.f;
    float acc[4][4];
    #pragma unroll
    for (int i = 0; i < 4; i++)
        #pragma unroll
        for (int j = 0; j < 4; j++) acc[i][j] = 0.f;

    const float4* xg = (const float4*)(x_cpm + (size_t)row0 * NCH);

    for (int c = 0; c < 8; c++) {
        __syncthreads();   // prior chunk's reads complete
        // stage x chunk: 1024 float4
        #pragma unroll
        for (int j = 0; j < 4; j++) {
            int idx = tid + j * BDIM;
            int r = idx >> 4, c16 = idx & 15;
            *(float4*)(s_xb + r * XBS + 4 * c16) = xg[r * 128 + c * 16 + c16];
        }
        // stage w1 chunk: 1024 float4
        #pragma unroll
        for (int j = 0; j < 4; j++) {
            int idx = tid + j * BDIM;
            int kk = idx >> 4, h4 = idx & 15;
            *(float4*)(s_wb + kk * 64 + 4 * h4) =
                ((const float4*)(g_w1t + (c * 64 + kk) * 64))[h4];
        }
        __syncthreads();

        // eps partial — R4-exact order: k = 64c + es + 4i, i ascending
        {
            const float* xr = s_xb + er * XBS;
            const float* cp = sm + F_CAP + c * 64;
            #pragma unroll 4
            for (int i = 0; i < 16; i++) {
                int k = es + 4 * i;
                pe = fmaf(xr[k], cp[k], pe);
            }
        }
        // GEMM1: 4 rows x 4 cols, kk ascending
        {
            const float* xb = s_xb + (4 * rg) * XBS;
            const float* wp = s_wb + 4 * cg;
            #pragma unroll 4
            for (int kk = 0; kk < 64; kk += 4) {
                float4 w0 = *(const float4*)(wp + (kk + 0) * 64);
                float4 w1 = *(const float4*)(wp + (kk + 1) * 64);
                float4 w2 = *(const float4*)(wp + (kk + 2) * 64);
                float4 w3 = *(const float4*)(wp + (kk + 3) * 64);
                #pragma unroll
                for (int r = 0; r < 4; r++) {
                    float4 a = *(const float4*)(xb + r * XBS + kk);
                    fma4(acc[r], a.x, w0); fma4(acc[r], a.y, w1);
                    fma4(acc[r], a.z, w2); fma4(acc[r], a.w, w3);
                }
            }
        }
    }

    // ---------------- P2: epsilon ----------------
    pe += __shfl_down_sync(0xffffffffu, pe, 2, 4);
    pe += __shfl_down_sync(0xffffffffu, pe, 1, 4);
    if (es == 0) sm[F_EPS + er] = pe;
    __syncthreads();
    const float cap_sum = sm[F_RED + 16];
    if (tid < TILE_M)
        sm[F_EPS + tid] = x_cons[row0 + tid] - sm[F_EPS + tid] / cap_sum;
    __syncthreads();

    // ---------------- P3: GEMM1 epilogue -> h1 ----------------
    {
        float4 we = *(const float4*)(g_w1t + 512 * 64 + 4 * cg);
        float4 bb = *(const float4*)(b1 + 4 * cg);
        #pragma unroll
        for (int r = 0; r < 4; r++) {
            float e = sm[F_EPS + 4 * rg + r];
            float4 h;
            h.x = fmaxf(acc[r][0] + e * we.x + bb.x, 0.f);
            h.y = fmaxf(acc[r][1] + e * we.y + bb.y, 0.f);
            h.z = fmaxf(acc[r][2] + e * we.z + bb.z, 0.f);
            h.w = fmaxf(acc[r][3] + e * we.w + bb.w, 0.f);
            *(float4*)(s_h1 + (4 * rg + r) * HS + 4 * cg) = h;
        }
    }

    // ---------------- P4: GEMM2 in 4 chunks of 128 cols + tanh -> g_t ----------------
    const int cg2 = tid & 31;    // 4 cols at 4*cg2
    const int rg2 = tid >> 5;    // warp id; rows 8rg2..8rg2+7
    float rs[8];
    #pragma unroll
    for (int i = 0; i < 8; i++) rs[i] = 0.f;

    for (int nc = 0; nc < NCH; nc += 128) {
        __syncthreads();
        // stage w2 chunk: 64 k x 128 cols, stride 132 floats
        #pragma unroll
        for (int j = 0; j < 8; j++) {
            int idx = tid + j * BDIM;
            int kk = idx >> 5, c4 = idx & 31;
            ((float4*)(sm + F_OV))[kk * W2F4 + c4] =
                ((const float4*)(g_w2t + kk * 512 + nc))[c4];
        }
        __syncthreads();

        float a2[8][4];
        #pragma unroll
        for (int r = 0; r < 8; r++)
            #pragma unroll
            for (int j = 0; j < 4; j++) a2[r][j] = 0.f;

        const float4* wp = ((const float4*)(sm + F_OV)) + cg2;
        const float*  hb = s_h1 + (8 * rg2) * HS;
        #pragma unroll 2
        for (int kk = 0; kk < HID; kk += 4) {
            float4 w0 = wp[(kk + 0) * W2F4];
            float4 w1 = wp[(kk + 1) * W2F4];
            float4 w2 = wp[(kk + 2) * W2F4];
            float4 w3 = wp[(kk + 3) * W2F4];
            #pragma unroll
            for (int r = 0; r < 8; r++) {
                float4 h = *(const float4*)(hb + r * HS + kk);   // broadcast (warp-uniform row)
                fma4(a2[r], h.x, w0); fma4(a2[r], h.y, w1);
                fma4(a2[r], h.z, w2); fma4(a2[r], h.w, w3);
            }
        }

        float4 bbv = *(const float4*)(b2 + nc + 4 * cg2);
        #pragma unroll
        for (int r = 0; r < 8; r++) {
            float4 t;
            t.x = fast_tanh(a2[r][0] + bbv.x);
            t.y = fast_tanh(a2[r][1] + bbv.y);
            t.z = fast_tanh(a2[r][2] + bbv.z);
            t.w = fast_tanh(a2[r][3] + bbv.w);
            rs[r] += (t.x + t.y) + (t.z + t.w);
            *(float4*)(g_t + (size_t)(row0 + 8 * rg2 + r) * NCH + nc + 4 * cg2) = t;
        }
    }

    // ---------------- P5: rowsums (one warp per 8 rows) -> scale ----------------
    #pragma unroll
    for (int r = 0; r < 8; r++) {
        float v = rs[r];
        #pragma unroll
        for (int off = 16; off; off >>= 1)
            v += __shfl_down_sync(0xffffffffu, v, off);
        if (cg2 == 0) sm[F_RS + 8 * rg2 + r] = v;
    }
    __syncthreads();
    if (tid < TILE_M)
        sm[F_SCALE + tid] = sm[F_EPS + tid] * cap_sum / sm[F_RS + tid];
    __syncthreads();

    // ---------------- P6: out = x + t * scale / cap ----------------
    for (int idx = tid; idx < TILE_M * (NCH / 4); idx += BDIM) {
        int r = idx >> 7, c4 = idx & 127;
        float4 xv = xg[r * 128 + c4];
        float4 tv = *(const float4*)(g_t + (size_t)(row0 + r) * NCH + 4 * c4);
        float4 ic = *(const float4*)(sm + F_ICAP + 4 * c4);
        float  sc = sm[F_SCALE + r];
        float4 o;
        o.x = fmaf(tv.x * sc, ic.x, xv.x);
        o.y = fmaf(tv.y * sc, ic.y, xv.y);
        o.z = fmaf(tv.z * sc, ic.z, xv.z);
        o.w = fmaf(tv.w * sc, ic.w, xv.w);
        *(float4*)(out + (size_t)(row0 + r) * NCH + 4 * c4) = o;
    }
}

extern "C" void kernel_launch(void* const* d_in, const int* in_sizes, int n_in,
                              void* d_out, int out_size) {
    const float* x_cpm  = (const float*)d_in[0];
    const float* x_cons = (const float*)d_in[1];
    const float* cap    = (const float*)d_in[2];
    const float* W1     = (const float*)d_in[3];
    const float* b1     = (const float*)d_in[4];
    const float* W2     = (const float*)d_in[5];
    const float* b2     = (const float*)d_in[6];
    float* out = (float*)d_out;

    cudaFuncSetAttribute(fused_kernel, cudaFuncAttributeMaxDynamicSharedMemorySize, SMEM_BYTES);

    prep_kernel<<<129, 256>>>(W1, W2);

    const int B = 65536;
    fused_kernel<<<B / TILE_M, BDIM, SMEM_BYTES>>>(x_cpm, x_cons, cap, b1, b2, out);
}